// round 14
// baseline (speedup 1.0000x reference)
#include <cuda_runtime.h>
#include <cuda_bf16.h>
#include <cstdint>

// DNGPU recurrence, round 13: unify rg onto the empirically fastest GEMM
// configuration (the cand one: M=64 x N=48, MI=1, 256 threads, 49.1K MMA/us
// vs 42.5K for every rg shape tried). rg grid becomes 512 (b x conv x mh x
// nq); gemm_run instantiation is byte-identical for both kernels. Same
// split products A0B0+A1B0+A0B1, 4-stage ring, pairwise barriers.

typedef __nv_bfloat16 bf16;
typedef __nv_bfloat162 bf162;

#define NB 32
#define NL 128
#define NC 192
#define PADL 130
#define KTOT 576
#define KCH 64
#define NCHUNK 27               // 1728 / 64
#define NPAIR 14
#define BROWS 48
#define BBYTES (BROWS * 128)    // 6144

__device__ bf16 g_wt[3 * 2 * NC * KTOT];           // [conv][term][co][k*192+ci]
__device__ bf16 g_ma0[NB * PADL * NC], g_ma1[NB * PADL * NC];
__device__ bf16 g_mb0[NB * PADL * NC], g_mb1[NB * PADL * NC];
__device__ bf16 g_t0[NB * PADL * NC], g_t1[NB * PADL * NC];
__device__ float g_gate[NB * NL * NC];

#define CP16(d, s) \
    asm volatile("cp.async.cg.shared.global [%0], [%1], 16;" :: "r"(d), "l"(s))
#define CP_COMMIT() asm volatile("cp.async.commit_group;" ::: "memory")
#define CP_WAIT(n) asm volatile("cp.async.wait_group %0;" :: "n"(n) : "memory")

__device__ __forceinline__ uint32_t smem_u32(const void* p) {
    uint32_t a;
    asm("{ .reg .u64 t; cvta.to.shared.u64 t, %1; cvt.u32.u64 %0, t; }"
        : "=r"(a) : "l"(p));
    return a;
}
__device__ __forceinline__ void ldsm4(uint32_t (&r)[4], uint32_t a) {
    asm volatile("ldmatrix.sync.aligned.m8n8.x4.shared.b16 {%0,%1,%2,%3}, [%4];"
                 : "=r"(r[0]), "=r"(r[1]), "=r"(r[2]), "=r"(r[3]) : "r"(a));
}
__device__ __forceinline__ void ldsm2(uint32_t (&r)[2], uint32_t a) {
    asm volatile("ldmatrix.sync.aligned.m8n8.x2.shared.b16 {%0,%1}, [%2];"
                 : "=r"(r[0]), "=r"(r[1]) : "r"(a));
}
__device__ __forceinline__ void mma16816(float (&c)[4], const uint32_t (&a)[4],
                                         uint32_t b0, uint32_t b1) {
    asm volatile(
        "mma.sync.aligned.m16n8k16.row.col.f32.bf16.bf16.f32 "
        "{%0,%1,%2,%3}, {%4,%5,%6,%7}, {%8,%9}, {%0,%1,%2,%3};"
        : "+f"(c[0]), "+f"(c[1]), "+f"(c[2]), "+f"(c[3])
        : "r"(a[0]), "r"(a[1]), "r"(a[2]), "r"(a[3]), "r"(b0), "r"(b1));
}
__device__ __forceinline__ void split2(float v0, float v1, bf162& hp, bf162& lp) {
    bf16 h0 = __float2bfloat16(v0);
    bf16 h1 = __float2bfloat16(v1);
    hp.x = h0; hp.y = h1;
    lp.x = __float2bfloat16(v0 - __bfloat162float(h0));
    lp.y = __float2bfloat16(v1 - __bfloat162float(h1));
}

// Full K=1728 (3 products x 576) GEMM, M=64 x N=48 CTA tile, 256 threads
// (4 mw x 2 nw), warp tile 16x24. Stage: [A: 64*128B][B: 48*128B], 128B
// rows, 16B units, unit swizzle u ^= (row & 7). 4-stage ring, pairwise wait.
__device__ __forceinline__ void gemm_run(char* ring,
                                         const bf16* __restrict__ a0,
                                         const bf16* __restrict__ a1,
                                         const bf16* __restrict__ b0,
                                         const bf16* __restrict__ b1,
                                         int tx, float (&acc)[3][4]) {
    const uint32_t sbase = smem_u32(ring);
    constexpr int AB = 64 * 128;
    constexpr int STB = AB + BBYTES;    // 14336
    constexpr int AJ = 2;               // 512 A transfers / 256 threads
    constexpr int BOPS = BROWS * 8;     // 384
    const int wid = tx >> 5, lane = tx & 31;
    const int mw = wid >> 1, nw = wid & 1;

    // ---- precomputed cp.async offsets
    uint32_t dA[AJ]; int sAo[AJ];
#pragma unroll
    for (int j = 0; j < AJ; j++) {
        int idx = tx + j * 256, r = idx >> 3, u = idx & 7;
        dA[j] = r * 128 + (((u ^ (r & 7))) << 4);
        sAo[j] = r * NC + u * 8;
    }
    uint32_t dB0; int sBo0; uint32_t dB1; int sBo1; bool vB1;
    {
        int r = tx >> 3, u = tx & 7;
        dB0 = AB + r * 128 + (((u ^ (r & 7))) << 4);
        sBo0 = r * KTOT + u * 8;
        int idx = tx + 256;
        vB1 = idx < BOPS;
        int r1 = (idx < BOPS ? idx : 0) >> 3, u1 = idx & 7;
        dB1 = AB + r1 * 128 + (((u1 ^ (r1 & 7))) << 4);
        sBo1 = r1 * KTOT + u1 * 8;
    }

    // ---- precomputed ldmatrix fragment offsets
    uint32_t offA[4], offB4[4], offB2[4];
    {
        int row = mw * 16 + ((lane >> 3) & 1) * 8 + (lane & 7);
#pragma unroll
        for (int h = 0; h < 4; h++)
            offA[h] = row * 128 + (((2 * h + (lane >> 4)) ^ (row & 7)) << 4);
        // B x4: tiles (j2=0,k0),(j2=0,k1),(j2=1,k0),(j2=1,k1) via lane groups
        int grp = lane >> 3;
        int j2s = grp >> 1, khs = grp & 1;
        int nrow = nw * 24 + j2s * 8 + (lane & 7);
#pragma unroll
        for (int h = 0; h < 4; h++)
            offB4[h] = AB + nrow * 128 + (((2 * h + khs) ^ (nrow & 7)) << 4);
        // B x2: tile j2=2, two k-halves via lane groups 0,1
        int nrow2 = nw * 24 + 16 + (lane & 7);
        int kh2 = (lane >> 3) & 1;
#pragma unroll
        for (int h = 0; h < 4; h++)
            offB2[h] = AB + nrow2 * 128 + (((2 * h + kh2) ^ (nrow2 & 7)) << 4);
    }

    // ---- chunk issue: q -> product p, tap, ci0; one commit group per chunk
    auto issue = [&](int q) {
        int p = q / 9, kc = q % 9;
        const bf16* ap = ((p == 1) ? a1 : a0) + (kc / 3) * NC + (kc % 3) * KCH;
        const bf16* bp = ((p == 2) ? b1 : b0) + kc * KCH;
        uint32_t st = sbase + (uint32_t)(q & 3) * STB;
#pragma unroll
        for (int j = 0; j < AJ; j++) CP16(st + dA[j], ap + sAo[j]);
        CP16(st + dB0, bp + sBo0);
        if (vB1) CP16(st + dB1, bp + sBo1);
        CP_COMMIT();
    };

    auto compute = [&](int q) {
        const uint32_t st = sbase + (uint32_t)(q & 3) * STB;
#pragma unroll
        for (int h = 0; h < 4; h++) {
            uint32_t af[4];
            ldsm4(af, st + offA[h]);
            uint32_t bq[4];
            ldsm4(bq, st + offB4[h]);
            uint32_t b2[2];
            ldsm2(b2, st + offB2[h]);
            mma16816(acc[0], af, bq[0], bq[1]);
            mma16816(acc[1], af, bq[2], bq[3]);
            mma16816(acc[2], af, b2[0], b2[1]);
        }
    };

    issue(0);
    issue(1);

#pragma unroll 1
    for (int P = 0; P < NPAIR; P++) {
        const int q = 2 * P;
        CP_WAIT(0);                 // chunks q and q+1 landed
        __syncthreads();            // release of stages q+2,q+3
        if (q + 2 < NCHUNK) issue(q + 2);
        if (q + 3 < NCHUNK) issue(q + 3);
        compute(q);
        if (q + 1 < NCHUNK) compute(q + 1);
    }
}

__device__ __forceinline__ float sigm(float x) { return 1.0f / (1.0f + expf(-x)); }

// ---------------- per-step kernels ----------------
// rg: 256 threads, tile M=64 x N=48, grid 512 (b x conv x mh x nq).
__global__ void __launch_bounds__(256, 2)
rg_kernel(const bf16* __restrict__ cur0, const bf16* __restrict__ cur1,
          const float* __restrict__ br, const float* __restrict__ bg) {
    extern __shared__ char ring[];
    const int tx = threadIdx.x, bx = blockIdx.x;
    const int nq = bx & 3, mh = (bx >> 2) & 1, conv = (bx >> 3) & 1, b = bx >> 4;
    const int r0 = mh * 64;
    const bf16* a0 = cur0 + ((size_t)b * PADL + r0) * NC;
    const bf16* a1 = cur1 + ((size_t)b * PADL + r0) * NC;
    const bf16* w0 = g_wt + ((size_t)(conv * 2 + 0) * NC + nq * BROWS) * KTOT;
    const bf16* w1 = g_wt + ((size_t)(conv * 2 + 1) * NC + nq * BROWS) * KTOT;

    float acc[3][4];
#pragma unroll
    for (int j = 0; j < 3; j++)
#pragma unroll
        for (int k = 0; k < 4; k++) acc[j][k] = 0.0f;

    gemm_run(ring, a0, a1, w0, w1, tx, acc);

    const float* bias = conv ? bg : br;
    const int wid = tx >> 5, lane = tx & 31;
    const int mw = wid >> 1, nw = wid & 1;
    const int gr = lane >> 2, qc = (lane & 3) * 2;
#pragma unroll
    for (int jn = 0; jn < 3; jn++) {
        int ch = nq * BROWS + nw * 24 + jn * 8 + qc;
        float bv0 = bias[ch], bv1 = bias[ch + 1];
#pragma unroll
        for (int hf = 0; hf < 2; hf++) {
            int row = r0 + mw * 16 + gr + hf * 8;
            float s0 = sigm(acc[jn][hf * 2 + 0] + bv0);
            float s1 = sigm(acc[jn][hf * 2 + 1] + bv1);
            if (conv == 0) {
                size_t idx = ((size_t)b * PADL + row + 1) * NC + ch;
                bf162 h2 = *(const bf162*)(cur0 + idx);
                bf162 l2 = *(const bf162*)(cur1 + idx);
                float m0 = __bfloat162float(h2.x) + __bfloat162float(l2.x);
                float m1 = __bfloat162float(h2.y) + __bfloat162float(l2.y);
                bf162 hp, lp;
                split2(s0 * m0, s1 * m1, hp, lp);
                *(bf162*)(g_t0 + idx) = hp;
                *(bf162*)(g_t1 + idx) = lp;
            } else {
                float2 g2;
                g2.x = s0; g2.y = s1;
                *(float2*)(g_gate + ((size_t)b * NL + row) * NC + ch) = g2;
            }
        }
    }
}

// cand: unchanged (256 threads, tile M=64 x N=48, grid 256).
__global__ void __launch_bounds__(256, 2)
cand_kernel(const bf16* __restrict__ cur0, const bf16* __restrict__ cur1,
            bf16* __restrict__ nxt0, bf16* __restrict__ nxt1,
            const float* __restrict__ bc, float* __restrict__ outp, int last) {
    extern __shared__ char ring[];
    const int tx = threadIdx.x, bx = blockIdx.x;
    const int b = bx >> 3, mh = (bx >> 2) & 1, nq = bx & 3;
    const int r0 = mh * 64;
    const bf16* a0 = g_t0 + ((size_t)b * PADL + r0) * NC;
    const bf16* a1 = g_t1 + ((size_t)b * PADL + r0) * NC;
    const bf16* w0 = g_wt + ((size_t)(2 * 2 + 0) * NC + nq * BROWS) * KTOT;
    const bf16* w1 = g_wt + ((size_t)(2 * 2 + 1) * NC + nq * BROWS) * KTOT;

    float acc[3][4];
#pragma unroll
    for (int j = 0; j < 3; j++)
#pragma unroll
        for (int k = 0; k < 4; k++) acc[j][k] = 0.0f;

    gemm_run(ring, a0, a1, w0, w1, tx, acc);

    const int wid = tx >> 5, lane = tx & 31;
    const int mw = wid >> 1, nw = wid & 1;
    const int gr = lane >> 2, qc = (lane & 3) * 2;
#pragma unroll
    for (int jn = 0; jn < 3; jn++) {
        int ch = nq * BROWS + nw * 24 + jn * 8 + qc;
        float bv0 = bc[ch], bv1 = bc[ch + 1];
#pragma unroll
        for (int hf = 0; hf < 2; hf++) {
            int row = r0 + mw * 16 + gr + hf * 8;
            float c0 = tanhf(acc[jn][hf * 2 + 0] + bv0);
            float c1 = tanhf(acc[jn][hf * 2 + 1] + bv1);
            float2 g2 = *(const float2*)(g_gate + ((size_t)b * NL + row) * NC + ch);
            size_t sidx = ((size_t)b * PADL + row) * NC + ch;   // mem[row-1]
            bf162 sh2 = *(const bf162*)(cur0 + sidx);
            bf162 sl2 = *(const bf162*)(cur1 + sidx);
            float sh0 = __bfloat162float(sh2.x) + __bfloat162float(sl2.x);
            float sh1 = __bfloat162float(sh2.y) + __bfloat162float(sl2.y);
            float o0 = g2.x * sh0 + (1.0f - g2.x) * c0;
            float o1 = g2.y * sh1 + (1.0f - g2.y) * c1;
            size_t didx = ((size_t)b * PADL + row + 1) * NC + ch;
            bf162 hp, lp;
            split2(o0, o1, hp, lp);
            *(bf162*)(nxt0 + didx) = hp;
            *(bf162*)(nxt1 + didx) = lp;
            if (last) {
                float2 o;
                o.x = o0; o.y = o1;
                *(float2*)(outp + ((size_t)b * NL + row) * NC + ch) = o;
            }
        }
    }
}

// ---------------- prep kernels ----------------
__global__ void zero_kernel() {
    int idx = blockIdx.x * 256 + threadIdx.x;
    const int n4 = NB * PADL * NC / 8;
    if (idx < n4) {
        uint4 z = make_uint4(0, 0, 0, 0);
        ((uint4*)g_ma0)[idx] = z;
        ((uint4*)g_ma1)[idx] = z;
        ((uint4*)g_mb0)[idx] = z;
        ((uint4*)g_mb1)[idx] = z;
        ((uint4*)g_t0)[idx] = z;
        ((uint4*)g_t1)[idx] = z;
    }
}

__global__ void aprep_kernel(const float* __restrict__ x) {
    int idx = blockIdx.x * 256 + threadIdx.x;
    if (idx >= NB * NL * NC) return;
    int ch = idx % NC;
    int l = (idx / NC) % NL;
    int b = idx / (NC * NL);
    float v = x[idx];
    bf16 h = __float2bfloat16(v);
    bf16 lo = __float2bfloat16(v - __bfloat162float(h));
    size_t d = ((size_t)b * PADL + l + 1) * NC + ch;
    g_ma0[d] = h;
    g_ma1[d] = lo;
}

__global__ void wprep_kernel(const float* __restrict__ wr,
                             const float* __restrict__ wg,
                             const float* __restrict__ wc) {
    int idx = blockIdx.x * 256 + threadIdx.x;
    if (idx >= 3 * 3 * NC * NC) return;
    int co = idx % NC;
    int t = idx / NC;
    int ci = t % NC; t /= NC;
    int k = t % 3, c = t / 3;
    const float* w = (c == 0) ? wr : (c == 1) ? wg : wc;
    float v = w[((size_t)k * NC + ci) * NC + co];
    bf16 h = __float2bfloat16(v);
    bf16 lo = __float2bfloat16(v - __bfloat162float(h));
    size_t base = (size_t)k * NC + ci;
    g_wt[((size_t)(c * 2 + 0) * NC + co) * KTOT + base] = h;
    g_wt[((size_t)(c * 2 + 1) * NC + co) * KTOT + base] = lo;
}

extern "C" void kernel_launch(void* const* d_in, const int* in_sizes, int n_in,
                              void* d_out, int out_size) {
    const float* x  = (const float*)d_in[0];
    const float* wr = (const float*)d_in[1];
    const float* br = (const float*)d_in[2];
    const float* wg = (const float*)d_in[3];
    const float* bg = (const float*)d_in[4];
    const float* wc = (const float*)d_in[5];
    const float* bc = (const float*)d_in[6];
    float* out = (float*)d_out;

    bf16 *ma0, *ma1, *mb0, *mb1;
    cudaGetSymbolAddress((void**)&ma0, g_ma0);
    cudaGetSymbolAddress((void**)&ma1, g_ma1);
    cudaGetSymbolAddress((void**)&mb0, g_mb0);
    cudaGetSymbolAddress((void**)&mb1, g_mb1);

    const int SMEM = 4 * (64 * 128 + BBYTES);        // 57344
    cudaFuncSetAttribute(rg_kernel, cudaFuncAttributeMaxDynamicSharedMemorySize,
                         SMEM);
    cudaFuncSetAttribute(cand_kernel, cudaFuncAttributeMaxDynamicSharedMemorySize,
                         SMEM);

    zero_kernel<<<(NB * PADL * NC / 8 + 255) / 256, 256>>>();
    wprep_kernel<<<(3 * 3 * NC * NC + 255) / 256, 256>>>(wr, wg, wc);
    aprep_kernel<<<(NB * NL * NC + 255) / 256, 256>>>(x);

    for (int s = 0; s < NL; s++) {
        bf16* c0 = (s & 1) ? mb0 : ma0;
        bf16* c1 = (s & 1) ? mb1 : ma1;
        bf16* n0 = (s & 1) ? ma0 : mb0;
        bf16* n1 = (s & 1) ? ma1 : mb1;
        rg_kernel<<<512, 256, SMEM>>>(c0, c1, br, bg);
        cand_kernel<<<256, 256, SMEM>>>(c0, c1, n0, n1, bc, out,
                                        s == NL - 1 ? 1 : 0);
    }
}

// round 16
// speedup vs baseline: 1.2471x; 1.2471x over previous
#include <cuda_runtime.h>
#include <cuda_bf16.h>
#include <cstdint>

// DNGPU recurrence, round 15 (round-14 resubmit after broker infra failure;
// audited: no OOB, no divergent barriers, ring stages disjoint).
// R9 base (best, 5785us) + twin-chunk A reuse: split expansion
// A0B0 + A0B1 + A1B0 -- products 0 and 2 share operand A0. 18 chunks:
// 9 "twin" chunks stage one A (=a0) plus BOTH weight sets B0,B1 (one A
// cp.async + one A ldmatrix feeds two MMA sets), then 9 singles (A=a1, B0).
// A cp.async and A ldmatrix each drop 33% (total L1 wavefronts ~-15%);
// MMA count unchanged; 9 barrier pairs.

typedef __nv_bfloat16 bf16;
typedef __nv_bfloat162 bf162;

#define NB 32
#define NL 128
#define NC 192
#define PADL 130
#define KTOT 576
#define KCH 64
#define NCHUNK 18               // 9 twin + 9 single
#define NPAIR 9
#define BROWS 48
#define BBYTES (BROWS * 128)    // 6144

__device__ bf16 g_wt[3 * 2 * NC * KTOT];           // [conv][term][co][k*192+ci]
__device__ bf16 g_ma0[NB * PADL * NC], g_ma1[NB * PADL * NC];
__device__ bf16 g_mb0[NB * PADL * NC], g_mb1[NB * PADL * NC];
__device__ bf16 g_t0[NB * PADL * NC], g_t1[NB * PADL * NC];
__device__ float g_gate[NB * NL * NC];

#define CP16(d, s) \
    asm volatile("cp.async.cg.shared.global [%0], [%1], 16;" :: "r"(d), "l"(s))
#define CP_COMMIT() asm volatile("cp.async.commit_group;" ::: "memory")
#define CP_WAIT(n) asm volatile("cp.async.wait_group %0;" :: "n"(n) : "memory")

__device__ __forceinline__ uint32_t smem_u32(const void* p) {
    uint32_t a;
    asm("{ .reg .u64 t; cvta.to.shared.u64 t, %1; cvt.u32.u64 %0, t; }"
        : "=r"(a) : "l"(p));
    return a;
}
__device__ __forceinline__ void ldsm4(uint32_t (&r)[4], uint32_t a) {
    asm volatile("ldmatrix.sync.aligned.m8n8.x4.shared.b16 {%0,%1,%2,%3}, [%4];"
                 : "=r"(r[0]), "=r"(r[1]), "=r"(r[2]), "=r"(r[3]) : "r"(a));
}
__device__ __forceinline__ void ldsm2(uint32_t (&r)[2], uint32_t a) {
    asm volatile("ldmatrix.sync.aligned.m8n8.x2.shared.b16 {%0,%1}, [%2];"
                 : "=r"(r[0]), "=r"(r[1]) : "r"(a));
}
__device__ __forceinline__ void mma16816(float (&c)[4], const uint32_t (&a)[4],
                                         uint32_t b0, uint32_t b1) {
    asm volatile(
        "mma.sync.aligned.m16n8k16.row.col.f32.bf16.bf16.f32 "
        "{%0,%1,%2,%3}, {%4,%5,%6,%7}, {%8,%9}, {%0,%1,%2,%3};"
        : "+f"(c[0]), "+f"(c[1]), "+f"(c[2]), "+f"(c[3])
        : "r"(a[0]), "r"(a[1]), "r"(a[2]), "r"(a[3]), "r"(b0), "r"(b1));
}
__device__ __forceinline__ void split2(float v0, float v1, bf162& hp, bf162& lp) {
    bf16 h0 = __float2bfloat16(v0);
    bf16 h1 = __float2bfloat16(v1);
    hp.x = h0; hp.y = h1;
    lp.x = __float2bfloat16(v0 - __bfloat162float(h0));
    lp.y = __float2bfloat16(v1 - __bfloat162float(h1));
}

// Full K GEMM over 18 chunks (9 twin + 9 single). Stage layout:
// [A: M*128B][B0: 6144B][B1: 6144B], 128B rows, 16B units, swizzle
// u ^= (row & 7). 256 threads: (M/32) mw-warps x 2 nw (24 cols, NW=3).
template <int M, int MI>
__device__ __forceinline__ void gemm_run(char* ring,
                                         const bf16* __restrict__ a0,
                                         const bf16* __restrict__ a1,
                                         const bf16* __restrict__ b0,
                                         const bf16* __restrict__ b1,
                                         int tx, float (&acc)[MI][3][4]) {
    const uint32_t sbase = smem_u32(ring);
    constexpr int AB = M * 128;
    constexpr int STB = AB + 2 * BBYTES;    // stage: A + B0 + B1
    constexpr int AJ = M / 32;              // A transfers per thread
    constexpr int BOPS = BROWS * 8;         // 384
    const int wid = tx >> 5, lane = tx & 31;
    const int mw = wid >> 1, nw = wid & 1;

    // ---- precomputed cp.async offsets
    uint32_t dA[AJ]; int sAo[AJ];
#pragma unroll
    for (int j = 0; j < AJ; j++) {
        int idx = tx + j * 256, r = idx >> 3, u = idx & 7;
        dA[j] = r * 128 + (((u ^ (r & 7))) << 4);
        sAo[j] = r * NC + u * 8;
    }
    uint32_t dB0; int sBo0; uint32_t dB1; int sBo1; bool vB1;
    {
        int r = tx >> 3, u = tx & 7;
        dB0 = AB + r * 128 + (((u ^ (r & 7))) << 4);
        sBo0 = r * KTOT + u * 8;
        int idx = tx + 256;
        vB1 = idx < BOPS;
        int r1 = (idx < BOPS ? idx : 0) >> 3, u1 = idx & 7;
        dB1 = AB + r1 * 128 + (((u1 ^ (r1 & 7))) << 4);
        sBo1 = r1 * KTOT + u1 * 8;
    }

    // ---- precomputed ldmatrix fragment offsets
    uint32_t offA[MI][4], offB4[4], offB2[4];
#pragma unroll
    for (int im = 0; im < MI; im++) {
        int row = mw * (16 * MI) + im * 16 + ((lane >> 3) & 1) * 8 + (lane & 7);
#pragma unroll
        for (int h = 0; h < 4; h++)
            offA[im][h] = row * 128 + (((2 * h + (lane >> 4)) ^ (row & 7)) << 4);
    }
    {
        // B x4: tiles (j2=0,k0),(j2=0,k1),(j2=1,k0),(j2=1,k1) via lane groups
        int grp = lane >> 3;
        int j2s = grp >> 1, khs = grp & 1;
        int nrow = nw * 24 + j2s * 8 + (lane & 7);
#pragma unroll
        for (int h = 0; h < 4; h++)
            offB4[h] = AB + nrow * 128 + (((2 * h + khs) ^ (nrow & 7)) << 4);
        // B x2: tile j2=2, two k-halves via lane groups 0,1
        int nrow2 = nw * 24 + 16 + (lane & 7);
        int kh2 = (lane >> 3) & 1;
#pragma unroll
        for (int h = 0; h < 4; h++)
            offB2[h] = AB + nrow2 * 128 + (((2 * h + kh2) ^ (nrow2 & 7)) << 4);
    }

    // ---- chunk issue: q<9 twin (A=a0, stage B0+B1); q>=9 single (A=a1, B0)
    auto issue = [&](int q) {
        const bool twin = q < 9;
        const int kc = twin ? q : q - 9;
        const bf16* ap = (twin ? a0 : a1) + (kc / 3) * NC + (kc % 3) * KCH;
        uint32_t st = sbase + (uint32_t)(q & 3) * STB;
#pragma unroll
        for (int j = 0; j < AJ; j++) CP16(st + dA[j], ap + sAo[j]);
        const bf16* bp0 = b0 + kc * KCH;
        CP16(st + dB0, bp0 + sBo0);
        if (vB1) CP16(st + dB1, bp0 + sBo1);
        if (twin) {
            const bf16* bp1 = b1 + kc * KCH;
            CP16(st + dB0 + BBYTES, bp1 + sBo0);
            if (vB1) CP16(st + dB1 + BBYTES, bp1 + sBo1);
        }
        CP_COMMIT();
    };

    auto compute = [&](int q) {
        const bool twin = q < 9;
        const uint32_t st = sbase + (uint32_t)(q & 3) * STB;
#pragma unroll
        for (int h = 0; h < 4; h++) {
            uint32_t af[MI][4];
#pragma unroll
            for (int im = 0; im < MI; im++) ldsm4(af[im], st + offA[im][h]);
            uint32_t bq[4];
            ldsm4(bq, st + offB4[h]);
            uint32_t b2[2];
            ldsm2(b2, st + offB2[h]);
#pragma unroll
            for (int im = 0; im < MI; im++) {
                mma16816(acc[im][0], af[im], bq[0], bq[1]);
                mma16816(acc[im][1], af[im], bq[2], bq[3]);
                mma16816(acc[im][2], af[im], b2[0], b2[1]);
            }
            if (twin) {
                uint32_t cq[4];
                ldsm4(cq, st + offB4[h] + BBYTES);
                uint32_t c2[2];
                ldsm2(c2, st + offB2[h] + BBYTES);
#pragma unroll
                for (int im = 0; im < MI; im++) {
                    mma16816(acc[im][0], af[im], cq[0], cq[1]);
                    mma16816(acc[im][1], af[im], cq[2], cq[3]);
                    mma16816(acc[im][2], af[im], c2[0], c2[1]);
                }
            }
        }
    };

    issue(0);
    issue(1);

#pragma unroll 1
    for (int P = 0; P < NPAIR; P++) {
        const int q = 2 * P;
        CP_WAIT(0);                 // chunks q and q+1 landed
        __syncthreads();            // release of stages q+2,q+3
        if (q + 2 < NCHUNK) issue(q + 2);
        if (q + 3 < NCHUNK) issue(q + 3);
        compute(q);
        compute(q + 1);
    }
}

__device__ __forceinline__ float sigm(float x) { return 1.0f / (1.0f + expf(-x)); }

// ---------------- per-step kernels ----------------
// rg: 256 threads, tile M=128 x N=48, grid 256 (b x conv x nq).
__global__ void __launch_bounds__(256, 2)
rg_kernel(const bf16* __restrict__ cur0, const bf16* __restrict__ cur1,
          const float* __restrict__ br, const float* __restrict__ bg) {
    extern __shared__ char ring[];
    const int tx = threadIdx.x, bx = blockIdx.x;
    const int b = bx >> 3, conv = (bx >> 2) & 1, nq = bx & 3;
    const bf16* a0 = cur0 + (size_t)b * PADL * NC;
    const bf16* a1 = cur1 + (size_t)b * PADL * NC;
    const bf16* w0 = g_wt + ((size_t)(conv * 2 + 0) * NC + nq * BROWS) * KTOT;
    const bf16* w1 = g_wt + ((size_t)(conv * 2 + 1) * NC + nq * BROWS) * KTOT;

    float acc[2][3][4];
#pragma unroll
    for (int i = 0; i < 2; i++)
#pragma unroll
        for (int j = 0; j < 3; j++)
#pragma unroll
            for (int k = 0; k < 4; k++) acc[i][j][k] = 0.0f;

    gemm_run<128, 2>(ring, a0, a1, w0, w1, tx, acc);

    const float* bias = conv ? bg : br;
    const int wid = tx >> 5, lane = tx & 31;
    const int mw = wid >> 1, nw = wid & 1;
    const int gr = lane >> 2, qc = (lane & 3) * 2;
#pragma unroll
    for (int im = 0; im < 2; im++) {
#pragma unroll
        for (int jn = 0; jn < 3; jn++) {
            int ch = nq * BROWS + nw * 24 + jn * 8 + qc;
            float bv0 = bias[ch], bv1 = bias[ch + 1];
#pragma unroll
            for (int hf = 0; hf < 2; hf++) {
                int row = mw * 32 + im * 16 + gr + hf * 8;
                float s0 = sigm(acc[im][jn][hf * 2 + 0] + bv0);
                float s1 = sigm(acc[im][jn][hf * 2 + 1] + bv1);
                if (conv == 0) {
                    size_t idx = ((size_t)b * PADL + row + 1) * NC + ch;
                    bf162 h2 = *(const bf162*)(cur0 + idx);
                    bf162 l2 = *(const bf162*)(cur1 + idx);
                    float m0 = __bfloat162float(h2.x) + __bfloat162float(l2.x);
                    float m1 = __bfloat162float(h2.y) + __bfloat162float(l2.y);
                    bf162 hp, lp;
                    split2(s0 * m0, s1 * m1, hp, lp);
                    *(bf162*)(g_t0 + idx) = hp;
                    *(bf162*)(g_t1 + idx) = lp;
                } else {
                    float2 g2;
                    g2.x = s0; g2.y = s1;
                    *(float2*)(g_gate + ((size_t)b * NL + row) * NC + ch) = g2;
                }
            }
        }
    }
}

// cand: 256 threads, tile M=64 x N=48, grid 256 (b x mh x nq).
__global__ void __launch_bounds__(256, 2)
cand_kernel(const bf16* __restrict__ cur0, const bf16* __restrict__ cur1,
            bf16* __restrict__ nxt0, bf16* __restrict__ nxt1,
            const float* __restrict__ bc, float* __restrict__ outp, int last) {
    extern __shared__ char ring[];
    const int tx = threadIdx.x, bx = blockIdx.x;
    const int b = bx >> 3, mh = (bx >> 2) & 1, nq = bx & 3;
    const int r0 = mh * 64;
    const bf16* a0 = g_t0 + ((size_t)b * PADL + r0) * NC;
    const bf16* a1 = g_t1 + ((size_t)b * PADL + r0) * NC;
    const bf16* w0 = g_wt + ((size_t)(2 * 2 + 0) * NC + nq * BROWS) * KTOT;
    const bf16* w1 = g_wt + ((size_t)(2 * 2 + 1) * NC + nq * BROWS) * KTOT;

    float acc[1][3][4];
#pragma unroll
    for (int j = 0; j < 3; j++)
#pragma unroll
        for (int k = 0; k < 4; k++) acc[0][j][k] = 0.0f;

    gemm_run<64, 1>(ring, a0, a1, w0, w1, tx, acc);

    const int wid = tx >> 5, lane = tx & 31;
    const int mw = wid >> 1, nw = wid & 1;
    const int gr = lane >> 2, qc = (lane & 3) * 2;
#pragma unroll
    for (int jn = 0; jn < 3; jn++) {
        int ch = nq * BROWS + nw * 24 + jn * 8 + qc;
        float bv0 = bc[ch], bv1 = bc[ch + 1];
#pragma unroll
        for (int hf = 0; hf < 2; hf++) {
            int row = r0 + mw * 16 + gr + hf * 8;
            float c0 = tanhf(acc[0][jn][hf * 2 + 0] + bv0);
            float c1 = tanhf(acc[0][jn][hf * 2 + 1] + bv1);
            float2 g2 = *(const float2*)(g_gate + ((size_t)b * NL + row) * NC + ch);
            size_t sidx = ((size_t)b * PADL + row) * NC + ch;   // mem[row-1]
            bf162 sh2 = *(const bf162*)(cur0 + sidx);
            bf162 sl2 = *(const bf162*)(cur1 + sidx);
            float sh0 = __bfloat162float(sh2.x) + __bfloat162float(sl2.x);
            float sh1 = __bfloat162float(sh2.y) + __bfloat162float(sl2.y);
            float o0 = g2.x * sh0 + (1.0f - g2.x) * c0;
            float o1 = g2.y * sh1 + (1.0f - g2.y) * c1;
            size_t didx = ((size_t)b * PADL + row + 1) * NC + ch;
            bf162 hp, lp;
            split2(o0, o1, hp, lp);
            *(bf162*)(nxt0 + didx) = hp;
            *(bf162*)(nxt1 + didx) = lp;
            if (last) {
                float2 o;
                o.x = o0; o.y = o1;
                *(float2*)(outp + ((size_t)b * NL + row) * NC + ch) = o;
            }
        }
    }
}

// ---------------- prep kernels ----------------
__global__ void zero_kernel() {
    int idx = blockIdx.x * 256 + threadIdx.x;
    const int n4 = NB * PADL * NC / 8;
    if (idx < n4) {
        uint4 z = make_uint4(0, 0, 0, 0);
        ((uint4*)g_ma0)[idx] = z;
        ((uint4*)g_ma1)[idx] = z;
        ((uint4*)g_mb0)[idx] = z;
        ((uint4*)g_mb1)[idx] = z;
        ((uint4*)g_t0)[idx] = z;
        ((uint4*)g_t1)[idx] = z;
    }
}

__global__ void aprep_kernel(const float* __restrict__ x) {
    int idx = blockIdx.x * 256 + threadIdx.x;
    if (idx >= NB * NL * NC) return;
    int ch = idx % NC;
    int l = (idx / NC) % NL;
    int b = idx / (NC * NL);
    float v = x[idx];
    bf16 h = __float2bfloat16(v);
    bf16 lo = __float2bfloat16(v - __bfloat162float(h));
    size_t d = ((size_t)b * PADL + l + 1) * NC + ch;
    g_ma0[d] = h;
    g_ma1[d] = lo;
}

__global__ void wprep_kernel(const float* __restrict__ wr,
                             const float* __restrict__ wg,
                             const float* __restrict__ wc) {
    int idx = blockIdx.x * 256 + threadIdx.x;
    if (idx >= 3 * 3 * NC * NC) return;
    int co = idx % NC;
    int t = idx / NC;
    int ci = t % NC; t /= NC;
    int k = t % 3, c = t / 3;
    const float* w = (c == 0) ? wr : (c == 1) ? wg : wc;
    float v = w[((size_t)k * NC + ci) * NC + co];
    bf16 h = __float2bfloat16(v);
    bf16 lo = __float2bfloat16(v - __bfloat162float(h));
    size_t base = (size_t)k * NC + ci;
    g_wt[((size_t)(c * 2 + 0) * NC + co) * KTOT + base] = h;
    g_wt[((size_t)(c * 2 + 1) * NC + co) * KTOT + base] = lo;
}

extern "C" void kernel_launch(void* const* d_in, const int* in_sizes, int n_in,
                              void* d_out, int out_size) {
    const float* x  = (const float*)d_in[0];
    const float* wr = (const float*)d_in[1];
    const float* br = (const float*)d_in[2];
    const float* wg = (const float*)d_in[3];
    const float* bg = (const float*)d_in[4];
    const float* wc = (const float*)d_in[5];
    const float* bc = (const float*)d_in[6];
    float* out = (float*)d_out;

    bf16 *ma0, *ma1, *mb0, *mb1;
    cudaGetSymbolAddress((void**)&ma0, g_ma0);
    cudaGetSymbolAddress((void**)&ma1, g_ma1);
    cudaGetSymbolAddress((void**)&mb0, g_mb0);
    cudaGetSymbolAddress((void**)&mb1, g_mb1);

    const int RG_SMEM = 4 * (128 * 128 + 2 * BBYTES);    // 114688
    const int CD_SMEM = 4 * (64 * 128 + 2 * BBYTES);     // 81920
    cudaFuncSetAttribute(rg_kernel, cudaFuncAttributeMaxDynamicSharedMemorySize,
                         RG_SMEM);
    cudaFuncSetAttribute(cand_kernel, cudaFuncAttributeMaxDynamicSharedMemorySize,
                         CD_SMEM);

    zero_kernel<<<(NB * PADL * NC / 8 + 255) / 256, 256>>>();
    wprep_kernel<<<(3 * 3 * NC * NC + 255) / 256, 256>>>(wr, wg, wc);
    aprep_kernel<<<(NB * NL * NC + 255) / 256, 256>>>(x);

    for (int s = 0; s < NL; s++) {
        bf16* c0 = (s & 1) ? mb0 : ma0;
        bf16* c1 = (s & 1) ? mb1 : ma1;
        bf16* n0 = (s & 1) ? ma0 : mb0;
        bf16* n1 = (s & 1) ? ma1 : mb1;
        rg_kernel<<<256, 256, RG_SMEM>>>(c0, c1, br, bg);
        cand_kernel<<<256, 256, CD_SMEM>>>(c0, c1, n0, n1, bc, out,
                                           s == NL - 1 ? 1 : 0);
    }
}